// round 1
// baseline (speedup 1.0000x reference)
#include <cuda_runtime.h>

#define BATCH 16
#define CIN   512
#define MID   128
#define GRP   4
#define H     56
#define W     56
#define HW    (H*W)
#define MH    7
#define MW    7
#define EPSV  1e-5f

// Scratch: post-mask intermediate activations (device globals, no alloc).
__device__ float g_y1[BATCH * MID * HW];   // relu(bn1(conv1(x*m))) * m
__device__ float g_y2[BATCH * MID * HW];   // relu(bn2(conv2(y1))) * m

// ---------------------------------------------------------------------------
// Kernel 1: 1x1 grouped conv (512->128, G=4) + BN + ReLU + mask2, per 8x8 tile.
// grid = (49, G, B), 256 thr. Each thread: px = t&63, 8 output channels.
// ---------------------------------------------------------------------------
__global__ __launch_bounds__(256) void k1_conv1(
    const float* __restrict__ x, const float* __restrict__ mask,
    const float* __restrict__ w1,
    const float* __restrict__ g1, const float* __restrict__ b1,
    const float* __restrict__ m1, const float* __restrict__ v1)
{
    const int bh = blockIdx.x / 7, bw = blockIdx.x % 7;
    const int g = blockIdx.y, b = blockIdx.z;
    const int h0 = bh * 8, w0 = bw * 8;
    const int t = threadIdx.x;
    const int px = t & 63;           // pixel in 8x8 tile
    const int ocq = t >> 6;          // 0..3 -> oc block of 8
    const int r = px >> 3, c = px & 7;

    const float m = mask[((b * GRP + g) * MH + bh) * MW + bw];

    if (m == 0.0f) {
        // entire group's post-mask activation is exactly zero
        #pragma unroll
        for (int k = 0; k < 8; k++) {
            int oc = ocq * 8 + k;
            g_y1[((b * MID + g * 32 + oc) * H + h0 + r) * W + w0 + c] = 0.0f;
        }
        return;
    }

    __shared__ float w_s[32][128];   // 16 KB
    __shared__ float x_s[32][64];    // 8 KB (ic chunk of 32)

    // load this group's weight slab: w1[(g*32+oc)*128 + ic]
    const float* w1g = w1 + (g * 32) * 128;
    for (int i = t; i < 32 * 128; i += 256)
        w_s[i >> 7][i & 127] = w1g[i];

    float acc[8] = {0,0,0,0,0,0,0,0};

    for (int cc = 0; cc < 4; cc++) {          // ic chunks of 32
        __syncthreads();
        for (int i = t; i < 32 * 64; i += 256) {
            int ic = i >> 6, p = i & 63;
            int rr = p >> 3, c2 = p & 7;
            x_s[ic][p] = x[((b * CIN + g * 128 + cc * 32 + ic) * H + h0 + rr) * W + w0 + c2];
        }
        __syncthreads();
        #pragma unroll
        for (int ic = 0; ic < 32; ic++) {
            float xv = x_s[ic][px];
            #pragma unroll
            for (int k = 0; k < 8; k++)
                acc[k] += w_s[ocq * 8 + k][cc * 32 + ic] * xv;
        }
    }

    #pragma unroll
    for (int k = 0; k < 8; k++) {
        int gc = g * 32 + ocq * 8 + k;
        float sc = g1[gc] * rsqrtf(v1[gc] + EPSV);
        float bi = b1[gc] - m1[gc] * sc;
        float v = fmaxf(acc[k] * sc + bi, 0.0f);   // mask2==1 here
        g_y1[((b * MID + gc) * H + h0 + r) * W + w0 + c] = v;
    }
}

// ---------------------------------------------------------------------------
// Kernel 2: 3x3 grouped conv (128->128, G=4, pad 1) + BN + ReLU + mask2(out).
// grid = (49, G, B), 256 thr. Halo 10x10 per group staged in smem.
// ---------------------------------------------------------------------------
__global__ __launch_bounds__(256) void k2_conv2(
    const float* __restrict__ mask,
    const float* __restrict__ w2,
    const float* __restrict__ g2, const float* __restrict__ b2,
    const float* __restrict__ m2, const float* __restrict__ v2)
{
    const int bh = blockIdx.x / 7, bw = blockIdx.x % 7;
    const int g = blockIdx.y, b = blockIdx.z;
    const int h0 = bh * 8, w0 = bw * 8;
    const int t = threadIdx.x;
    const int px = t & 63;
    const int ocq = t >> 6;
    const int r = px >> 3, c = px & 7;

    const float m = mask[((b * GRP + g) * MH + bh) * MW + bw];

    if (m == 0.0f) {
        #pragma unroll
        for (int k = 0; k < 8; k++) {
            int oc = ocq * 8 + k;
            g_y2[((b * MID + g * 32 + oc) * H + h0 + r) * W + w0 + c] = 0.0f;
        }
        return;
    }

    __shared__ float in_s[32][100];      // 12.8 KB: 32 ch x 10x10 halo
    __shared__ float w_s[32][16][9];     // 18.4 KB: oc x (ic chunk 16) x 3x3

    // load input halo (y1 is already post-mask; zero-pad image borders)
    for (int i = t; i < 32 * 100; i += 256) {
        int ic = i / 100, p = i % 100;
        int rr = h0 + p / 10 - 1, c2 = w0 + p % 10 - 1;
        float v = 0.0f;
        if (rr >= 0 && rr < H && c2 >= 0 && c2 < W)
            v = g_y1[((b * MID + g * 32 + ic) * H + rr) * W + c2];
        in_s[ic][p] = v;
    }

    float acc[8] = {0,0,0,0,0,0,0,0};

    const float* w2g = w2 + (g * 32) * 32 * 9;   // [oc=32][ic=32][9]

    for (int ch = 0; ch < 2; ch++) {             // ic chunks of 16
        __syncthreads();
        for (int i = t; i < 32 * 16 * 9; i += 256) {
            int oc = i / 144, rem = i % 144;
            int icc = rem / 9, kk = rem % 9;
            w_s[oc][icc][kk] = w2g[oc * 288 + (ch * 16 + icc) * 9 + kk];
        }
        __syncthreads();
        for (int icc = 0; icc < 16; icc++) {
            int ic = ch * 16 + icc;
            #pragma unroll
            for (int kr = 0; kr < 3; kr++) {
                #pragma unroll
                for (int kc = 0; kc < 3; kc++) {
                    float xv = in_s[ic][(r + kr) * 10 + (c + kc)];
                    #pragma unroll
                    for (int k = 0; k < 8; k++)
                        acc[k] += w_s[ocq * 8 + k][icc][kr * 3 + kc] * xv;
                }
            }
        }
    }

    #pragma unroll
    for (int k = 0; k < 8; k++) {
        int gc = g * 32 + ocq * 8 + k;
        float sc = g2[gc] * rsqrtf(v2[gc] + EPSV);
        float bi = b2[gc] - m2[gc] * sc;
        float v = fmaxf(acc[k] * sc + bi, 0.0f);   // * mask2 (==1)
        g_y2[((b * MID + gc) * H + h0 + r) * W + w0 + c] = v;
    }
}

// ---------------------------------------------------------------------------
// Kernel 3: 1x1 grouped conv (128->512, G=4) + BN + residual + ReLU.
// grid = (49, G, B), 256 thr. Each thread: px, 32 output channels.
// If mask==0: conv term is exactly zero -> out = relu(bias3 + x).
// ---------------------------------------------------------------------------
__global__ __launch_bounds__(256) void k3_conv3(
    const float* __restrict__ x, const float* __restrict__ mask,
    const float* __restrict__ w3,
    const float* __restrict__ g3, const float* __restrict__ b3,
    const float* __restrict__ m3, const float* __restrict__ v3,
    float* __restrict__ out)
{
    const int bh = blockIdx.x / 7, bw = blockIdx.x % 7;
    const int g = blockIdx.y, b = blockIdx.z;
    const int h0 = bh * 8, w0 = bw * 8;
    const int t = threadIdx.x;
    const int px = t & 63;
    const int ocq = t >> 6;          // 0..3 -> oc block of 32
    const int r = px >> 3, c = px & 7;

    const float m = mask[((b * GRP + g) * MH + bh) * MW + bw];

    if (m == 0.0f) {
        #pragma unroll
        for (int k = 0; k < 32; k++) {
            int gc = g * 128 + ocq * 32 + k;
            float sc = g3[gc] * rsqrtf(v3[gc] + EPSV);
            float bi = b3[gc] - m3[gc] * sc;
            long idx = ((long)(b * CIN + gc) * H + h0 + r) * W + w0 + c;
            out[idx] = fmaxf(bi + x[idx], 0.0f);
        }
        return;
    }

    __shared__ float w_s[128][32];   // 16 KB: this group's w3 [oc=128][ic=32]
    __shared__ float y_s[32][64];    // 8 KB

    const float* w3g = w3 + (g * 128) * 32;
    for (int i = t; i < 128 * 32; i += 256)
        w_s[i >> 5][i & 31] = w3g[i];
    for (int i = t; i < 32 * 64; i += 256) {
        int ic = i >> 6, p = i & 63;
        int rr = p >> 3, c2 = p & 7;
        y_s[ic][p] = g_y2[((b * MID + g * 32 + ic) * H + h0 + rr) * W + w0 + c2];
    }
    __syncthreads();

    float acc[32];
    #pragma unroll
    for (int k = 0; k < 32; k++) acc[k] = 0.0f;

    #pragma unroll
    for (int ic = 0; ic < 32; ic++) {
        float xv = y_s[ic][px];
        #pragma unroll
        for (int k = 0; k < 32; k++)
            acc[k] += w_s[ocq * 32 + k][ic] * xv;
    }

    #pragma unroll
    for (int k = 0; k < 32; k++) {
        int gc = g * 128 + ocq * 32 + k;
        float sc = g3[gc] * rsqrtf(v3[gc] + EPSV);
        float bi = b3[gc] - m3[gc] * sc;
        long idx = ((long)(b * CIN + gc) * H + h0 + r) * W + w0 + c;
        out[idx] = fmaxf(acc[k] * sc + bi + x[idx], 0.0f);
    }
}

// ---------------------------------------------------------------------------
extern "C" void kernel_launch(void* const* d_in, const int* in_sizes, int n_in,
                              void* d_out, int out_size)
{
    const float* x    = (const float*)d_in[0];
    const float* mask = (const float*)d_in[1];
    const float* w1   = (const float*)d_in[2];
    const float* g1   = (const float*)d_in[3];
    const float* b1   = (const float*)d_in[4];
    const float* m1   = (const float*)d_in[5];
    const float* v1   = (const float*)d_in[6];
    const float* w2   = (const float*)d_in[7];
    const float* g2   = (const float*)d_in[8];
    const float* b2   = (const float*)d_in[9];
    const float* m2   = (const float*)d_in[10];
    const float* v2   = (const float*)d_in[11];
    const float* w3   = (const float*)d_in[12];
    const float* g3   = (const float*)d_in[13];
    const float* b3   = (const float*)d_in[14];
    const float* m3   = (const float*)d_in[15];
    const float* v3   = (const float*)d_in[16];
    float* out = (float*)d_out;

    dim3 grid(49, GRP, BATCH);
    k1_conv1<<<grid, 256>>>(x, mask, w1, g1, b1, m1, v1);
    k2_conv2<<<grid, 256>>>(mask, w2, g2, b2, m2, v2);
    k3_conv3<<<grid, 256>>>(x, mask, w3, g3, b3, m3, v3, out);
}

// round 2
// speedup vs baseline: 1.5432x; 1.5432x over previous
#include <cuda_runtime.h>

#define BATCH 16
#define CIN   512
#define MID   128
#define GRP   4
#define H     56
#define W     56
#define HW    (H*W)
#define MH    7
#define MW    7
#define EPSV  1e-5f

// Scratch: post-mask intermediate activations (device globals, no alloc).
__device__ float g_y1[BATCH * MID * HW];   // relu(bn1(conv1(x*m))) * m
__device__ float g_y2[BATCH * MID * HW];   // relu(bn2(conv2(y1))) * m

// Thread mapping (all kernels): t = pxq*16 + ocp.
//   pxq in [0,16): 4 consecutive pixels in a row -> r = pxq>>1, cst = (pxq&1)*4
//   ocp in [0,16): output-channel slice

// ---------------------------------------------------------------------------
// Kernel 1: 1x1 grouped conv (512->128, G=4) + BN + ReLU (+mask2), 8x8 tile.
// Thread: 4 px x 2 oc. Inner per ic: LDS.128(x) + LDS.64(w) + 8 FFMA.
// ---------------------------------------------------------------------------
__global__ __launch_bounds__(256) void k1_conv1(
    const float* __restrict__ x, const float* __restrict__ mask,
    const float* __restrict__ w1,
    const float* __restrict__ g1, const float* __restrict__ b1,
    const float* __restrict__ m1, const float* __restrict__ v1)
{
    const int bh = blockIdx.x / 7, bw = blockIdx.x % 7;
    const int g = blockIdx.y, b = blockIdx.z;
    const int h0 = bh * 8, w0 = bw * 8;
    const int t = threadIdx.x;
    const int pxq = t >> 4, ocp = t & 15;
    const int r = pxq >> 1, cst = (pxq & 1) * 4;

    const float m = mask[((b * GRP + g) * MH + bh) * MW + bw];

    if (m == 0.0f) {
        const float4 z = make_float4(0.f, 0.f, 0.f, 0.f);
        #pragma unroll
        for (int k = 0; k < 2; k++) {
            int gc = g * 32 + ocp * 2 + k;
            *(float4*)&g_y1[((b * MID + gc) * H + h0 + r) * W + w0 + cst] = z;
        }
        return;
    }

    __shared__ float  w_s[128][34];     // [ic][oc], padded
    __shared__ float4 x_s[32][16];      // [ic][pxq] (chunk of 32 ic)

    // w1 group slab: w1[(g*32+oc)*128 + ic] -> w_s[ic][oc]
    const float* w1g = w1 + (g * 32) * 128;
    #pragma unroll
    for (int i = t; i < 32 * 128; i += 256)
        w_s[i & 127][i >> 7] = w1g[i];

    float acc[2][4] = {{0,0,0,0},{0,0,0,0}};

    for (int cc = 0; cc < 4; cc++) {     // ic chunks of 32
        // load 32 ic x 64 px as float4
        #pragma unroll
        for (int j = 0; j < 2; j++) {
            int i = t + j * 256;         // i in [0,512)
            int ic = i >> 4, p4 = i & 15;
            int rr = p4 >> 1, c2 = (p4 & 1) * 4;
            x_s[ic][p4] = *(const float4*)&x[
                ((b * CIN + g * 128 + cc * 32 + ic) * H + h0 + rr) * W + w0 + c2];
        }
        __syncthreads();
        #pragma unroll 8
        for (int ic = 0; ic < 32; ic++) {
            float4 xv = x_s[ic][pxq];
            float2 wv = *(float2*)&w_s[cc * 32 + ic][ocp * 2];
            acc[0][0] += wv.x * xv.x; acc[0][1] += wv.x * xv.y;
            acc[0][2] += wv.x * xv.z; acc[0][3] += wv.x * xv.w;
            acc[1][0] += wv.y * xv.x; acc[1][1] += wv.y * xv.y;
            acc[1][2] += wv.y * xv.z; acc[1][3] += wv.y * xv.w;
        }
        __syncthreads();
    }

    #pragma unroll
    for (int k = 0; k < 2; k++) {
        int gc = g * 32 + ocp * 2 + k;
        float sc = g1[gc] * rsqrtf(v1[gc] + EPSV);
        float bi = b1[gc] - m1[gc] * sc;
        float4 v;
        v.x = fmaxf(acc[k][0] * sc + bi, 0.0f);
        v.y = fmaxf(acc[k][1] * sc + bi, 0.0f);
        v.z = fmaxf(acc[k][2] * sc + bi, 0.0f);
        v.w = fmaxf(acc[k][3] * sc + bi, 0.0f);
        *(float4*)&g_y1[((b * MID + gc) * H + h0 + r) * W + w0 + cst] = v;
    }
}

// ---------------------------------------------------------------------------
// Kernel 2: 3x3 grouped conv (128->128, G=4, pad 1) + BN + ReLU + mask.
// Thread: 4 px x 2 oc. Per ic: 18 scalar LDS (x rows, register-shifted over
// kc) + 9 LDS.64 (w pairs) + 72 FFMA.
// ---------------------------------------------------------------------------
__global__ __launch_bounds__(256) void k2_conv2(
    const float* __restrict__ mask,
    const float* __restrict__ w2,
    const float* __restrict__ g2, const float* __restrict__ b2,
    const float* __restrict__ m2, const float* __restrict__ v2)
{
    const int bh = blockIdx.x / 7, bw = blockIdx.x % 7;
    const int g = blockIdx.y, b = blockIdx.z;
    const int h0 = bh * 8, w0 = bw * 8;
    const int t = threadIdx.x;
    const int pxq = t >> 4, ocp = t & 15;
    const int r = pxq >> 1, cst = (pxq & 1) * 4;

    const float m = mask[((b * GRP + g) * MH + bh) * MW + bw];

    if (m == 0.0f) {
        const float4 z = make_float4(0.f, 0.f, 0.f, 0.f);
        #pragma unroll
        for (int k = 0; k < 2; k++) {
            int gc = g * 32 + ocp * 2 + k;
            *(float4*)&g_y2[((b * MID + gc) * H + h0 + r) * W + w0 + cst] = z;
        }
        return;
    }

    __shared__ float in_s[32][100];        // 32 ch x 10x10 halo
    __shared__ float w_s[16][9][34];       // [icc][pos][oc], padded

    // halo (y1 already post-mask; zero-pad borders)
    for (int i = t; i < 32 * 100; i += 256) {
        int ic = i / 100, p = i % 100;
        int rr = h0 + p / 10 - 1, c2 = w0 + p % 10 - 1;
        float v = 0.0f;
        if (rr >= 0 && rr < H && c2 >= 0 && c2 < W)
            v = g_y1[((b * MID + g * 32 + ic) * H + rr) * W + c2];
        in_s[ic][p] = v;
    }

    float acc[2][4] = {{0,0,0,0},{0,0,0,0}};
    const float* w2g = w2 + (g * 32) * 32 * 9;   // [oc=32][ic=32][9]

    for (int ch = 0; ch < 2; ch++) {             // ic chunks of 16 (weights)
        if (ch) __syncthreads();
        for (int i = t; i < 32 * 16 * 9; i += 256) {
            int oc = i / 144, rem = i % 144;
            int icc = rem / 9, kk = rem % 9;
            w_s[icc][kk][oc] = w2g[oc * 288 + (ch * 16 + icc) * 9 + kk];
        }
        __syncthreads();

        for (int icc = 0; icc < 16; icc++) {
            int ic = ch * 16 + icc;
            float xr[3][6];
            #pragma unroll
            for (int kr = 0; kr < 3; kr++)
                #pragma unroll
                for (int j = 0; j < 6; j++)
                    xr[kr][j] = in_s[ic][(r + kr) * 10 + cst + j];
            #pragma unroll
            for (int kr = 0; kr < 3; kr++) {
                #pragma unroll
                for (int kc = 0; kc < 3; kc++) {
                    float2 wv = *(float2*)&w_s[icc][kr * 3 + kc][ocp * 2];
                    #pragma unroll
                    for (int q = 0; q < 4; q++) {
                        float xv = xr[kr][q + kc];
                        acc[0][q] += wv.x * xv;
                        acc[1][q] += wv.y * xv;
                    }
                }
            }
        }
    }

    #pragma unroll
    for (int k = 0; k < 2; k++) {
        int gc = g * 32 + ocp * 2 + k;
        float sc = g2[gc] * rsqrtf(v2[gc] + EPSV);
        float bi = b2[gc] - m2[gc] * sc;
        float4 v;
        v.x = fmaxf(acc[k][0] * sc + bi, 0.0f);
        v.y = fmaxf(acc[k][1] * sc + bi, 0.0f);
        v.z = fmaxf(acc[k][2] * sc + bi, 0.0f);
        v.w = fmaxf(acc[k][3] * sc + bi, 0.0f);
        *(float4*)&g_y2[((b * MID + gc) * H + h0 + r) * W + w0 + cst] = v;
    }
}

// ---------------------------------------------------------------------------
// Kernel 3: 1x1 grouped conv (128->512, G=4) + BN + residual + ReLU.
// Thread: 4 px x 8 oc. Per ic: LDS.128(x) + 2x LDS.128(w) + 32 FFMA.
// mask==0 -> out = relu(bias3 + x).
// ---------------------------------------------------------------------------
__global__ __launch_bounds__(256) void k3_conv3(
    const float* __restrict__ x, const float* __restrict__ mask,
    const float* __restrict__ w3,
    const float* __restrict__ g3, const float* __restrict__ b3,
    const float* __restrict__ m3, const float* __restrict__ v3,
    float* __restrict__ out)
{
    const int bh = blockIdx.x / 7, bw = blockIdx.x % 7;
    const int g = blockIdx.y, b = blockIdx.z;
    const int h0 = bh * 8, w0 = bw * 8;
    const int t = threadIdx.x;
    const int pxq = t >> 4, ocp = t & 15;
    const int r = pxq >> 1, cst = (pxq & 1) * 4;

    const float m = mask[((b * GRP + g) * MH + bh) * MW + bw];

    if (m == 0.0f) {
        #pragma unroll
        for (int k = 0; k < 8; k++) {
            int gc = g * 128 + ocp * 8 + k;
            float sc = g3[gc] * rsqrtf(v3[gc] + EPSV);
            float bi = b3[gc] - m3[gc] * sc;
            long idx = ((long)(b * CIN + gc) * H + h0 + r) * W + w0 + cst;
            float4 xv = *(const float4*)&x[idx];
            float4 v;
            v.x = fmaxf(bi + xv.x, 0.0f);
            v.y = fmaxf(bi + xv.y, 0.0f);
            v.z = fmaxf(bi + xv.z, 0.0f);
            v.w = fmaxf(bi + xv.w, 0.0f);
            *(float4*)&out[idx] = v;
        }
        return;
    }

    __shared__ float  w_s[32][132];     // [ic][oc], padded (row 528B, 16B-aligned)
    __shared__ float4 y_s[32][16];      // [ic][pxq]

    const float* w3g = w3 + (g * 128) * 32;     // [oc=128][ic=32]
    #pragma unroll
    for (int i = t; i < 128 * 32; i += 256)
        w_s[i & 31][i >> 5] = w3g[i];
    #pragma unroll
    for (int j = 0; j < 2; j++) {
        int i = t + j * 256;
        int ic = i >> 4, p4 = i & 15;
        int rr = p4 >> 1, c2 = (p4 & 1) * 4;
        y_s[ic][p4] = *(const float4*)&g_y2[
            ((b * MID + g * 32 + ic) * H + h0 + rr) * W + w0 + c2];
    }
    __syncthreads();

    float acc[8][4];
    #pragma unroll
    for (int k = 0; k < 8; k++)
        #pragma unroll
        for (int q = 0; q < 4; q++) acc[k][q] = 0.0f;

    #pragma unroll 4
    for (int ic = 0; ic < 32; ic++) {
        float4 xv = y_s[ic][pxq];
        const float* wr = &w_s[ic][ocp * 8];
        float4 wa = *(const float4*)wr;
        float4 wb = *(const float4*)(wr + 4);
        float wk[8] = {wa.x, wa.y, wa.z, wa.w, wb.x, wb.y, wb.z, wb.w};
        #pragma unroll
        for (int k = 0; k < 8; k++) {
            acc[k][0] += wk[k] * xv.x;
            acc[k][1] += wk[k] * xv.y;
            acc[k][2] += wk[k] * xv.z;
            acc[k][3] += wk[k] * xv.w;
        }
    }

    #pragma unroll
    for (int k = 0; k < 8; k++) {
        int gc = g * 128 + ocp * 8 + k;
        float sc = g3[gc] * rsqrtf(v3[gc] + EPSV);
        float bi = b3[gc] - m3[gc] * sc;
        long idx = ((long)(b * CIN + gc) * H + h0 + r) * W + w0 + cst;
        float4 xv = *(const float4*)&x[idx];
        float4 v;
        v.x = fmaxf(acc[k][0] * sc + bi + xv.x, 0.0f);
        v.y = fmaxf(acc[k][1] * sc + bi + xv.y, 0.0f);
        v.z = fmaxf(acc[k][2] * sc + bi + xv.z, 0.0f);
        v.w = fmaxf(acc[k][3] * sc + bi + xv.w, 0.0f);
        *(float4*)&out[idx] = v;
    }
}

// ---------------------------------------------------------------------------
extern "C" void kernel_launch(void* const* d_in, const int* in_sizes, int n_in,
                              void* d_out, int out_size)
{
    const float* x    = (const float*)d_in[0];
    const float* mask = (const float*)d_in[1];
    const float* w1   = (const float*)d_in[2];
    const float* g1   = (const float*)d_in[3];
    const float* b1   = (const float*)d_in[4];
    const float* m1   = (const float*)d_in[5];
    const float* v1   = (const float*)d_in[6];
    const float* w2   = (const float*)d_in[7];
    const float* g2   = (const float*)d_in[8];
    const float* b2   = (const float*)d_in[9];
    const float* m2   = (const float*)d_in[10];
    const float* v2   = (const float*)d_in[11];
    const float* w3   = (const float*)d_in[12];
    const float* g3   = (const float*)d_in[13];
    const float* b3   = (const float*)d_in[14];
    const float* m3   = (const float*)d_in[15];
    const float* v3   = (const float*)d_in[16];
    float* out = (float*)d_out;

    dim3 grid(49, GRP, BATCH);
    k1_conv1<<<grid, 256>>>(x, mask, w1, g1, b1, m1, v1);
    k2_conv2<<<grid, 256>>>(mask, w2, g2, b2, m2, v2);
    k3_conv3<<<grid, 256>>>(x, mask, w3, g3, b3, m3, v3, out);
}

// round 3
// speedup vs baseline: 1.7695x; 1.1466x over previous
#include <cuda_runtime.h>

#define BATCH 16
#define CIN   512
#define MID   128
#define GRP   4
#define H     56
#define W     56
#define HW    (H*W)
#define MH    7
#define MW    7
#define EPSV  1e-5f

// Scratch: post-mask intermediate activations (device globals, no alloc).
__device__ float g_y1[BATCH * MID * HW];   // relu(bn1(conv1(x*m))) * m
__device__ float g_y2[BATCH * MID * HW];   // relu(bn2(conv2(y1))) * m

// ---------------------------------------------------------------------------
// Kernel 1: 1x1 grouped conv (512->128) + BN + ReLU (+mask), 8x8 tile.
// CTA = (tile, group-pair, batch), 256 thr. Thread = 4px x 4oc.
// Per ic: LDS.128(x) + LDS.128(w) + 16 FFMA. x chunks ping-pong double-buffered
// with register prefetch. Group masks are warp-uniform (warps 0-3 = group A,
// warps 4-7 = group B) -> clean warp-level compute skip.
// ---------------------------------------------------------------------------
__global__ __launch_bounds__(256) void k1_conv1(
    const float* __restrict__ x, const float* __restrict__ mask,
    const float* __restrict__ w1,
    const float* __restrict__ g1, const float* __restrict__ b1,
    const float* __restrict__ m1, const float* __restrict__ v1)
{
    const int bh = blockIdx.x / 7, bw = blockIdx.x % 7;
    const int gp = blockIdx.y, b = blockIdx.z;      // gp: group pair (0/1)
    const int h0 = bh * 8, w0 = bw * 8;
    const int t = threadIdx.x;
    const int ocq = t >> 4;            // [0,16): 4-oc slice within 64 oc
    const int pxq = t & 15;            // [0,16): 4-px quad
    const int r = pxq >> 1, cst = (pxq & 1) * 4;

    const float m0 = mask[((b * GRP + gp * 2 + 0) * MH + bh) * MW + bw];
    const float m1v = mask[((b * GRP + gp * 2 + 1) * MH + bh) * MW + bw];

    if (m0 == 0.0f && m1v == 0.0f) {
        const float4 z = make_float4(0.f, 0.f, 0.f, 0.f);
        #pragma unroll
        for (int k = 0; k < 4; k++) {
            int gc = gp * 64 + ocq * 4 + k;
            *(float4*)&g_y1[((b * MID + gc) * H + h0 + r) * W + w0 + cst] = z;
        }
        return;
    }

    __shared__ float  w_s[128][68];        // [ic][oc 0..63], pad 68
    __shared__ float4 x_s[2][2][8][16];    // [buf][grp][icc][pxq]

    // weights for both groups: w1[(gp*64+oc)*128 + ic] -> w_s[ic][oc]
    const float* w1g = w1 + (gp * 64) * 128;
    #pragma unroll
    for (int i = t; i < 64 * 128; i += 256)
        w_s[i & 127][i >> 7] = w1g[i];

    // per-thread loader coords (1 float4 per chunk)
    const int sgg  = t >> 7;               // group of the ic being loaded
    const int sicc = (t >> 4) & 7;
    const int sp4  = t & 15;
    const int srr  = sp4 >> 1, sc2 = (sp4 & 1) * 4;
    const bool loadActive = (sgg ? m1v : m0) != 0.0f;
    const float* xbase = x + ((long)(b * CIN + (gp * 2 + sgg) * 128 + sicc) * H + h0 + srr) * W + w0 + sc2;

    const int myg = ocq >> 3;               // this thread's group (warp-uniform)
    const bool active = (myg ? m1v : m0) != 0.0f;

    float4 rld = make_float4(0.f, 0.f, 0.f, 0.f);
    if (loadActive) rld = *(const float4*)xbase;          // chunk 0
    x_s[0][sgg][sicc][sp4] = rld;
    __syncthreads();

    float acc[4][4];
    #pragma unroll
    for (int k = 0; k < 4; k++)
        #pragma unroll
        for (int q = 0; q < 4; q++) acc[k][q] = 0.0f;

    for (int cc = 0; cc < 16; cc++) {       // 16 chunks of 8 ic
        float4 rn = make_float4(0.f, 0.f, 0.f, 0.f);
        if (cc < 15 && loadActive)
            rn = *(const float4*)(xbase + (long)(cc + 1) * 8 * HW);

        if (active) {
            const int buf = cc & 1;
            #pragma unroll
            for (int icc = 0; icc < 8; icc++) {
                float4 xv = x_s[buf][myg][icc][pxq];
                float4 wv = *(const float4*)&w_s[cc * 8 + icc][ocq * 4];
                acc[0][0] += wv.x * xv.x; acc[0][1] += wv.x * xv.y;
                acc[0][2] += wv.x * xv.z; acc[0][3] += wv.x * xv.w;
                acc[1][0] += wv.y * xv.x; acc[1][1] += wv.y * xv.y;
                acc[1][2] += wv.y * xv.z; acc[1][3] += wv.y * xv.w;
                acc[2][0] += wv.z * xv.x; acc[2][1] += wv.z * xv.y;
                acc[2][2] += wv.z * xv.z; acc[2][3] += wv.z * xv.w;
                acc[3][0] += wv.w * xv.x; acc[3][1] += wv.w * xv.y;
                acc[3][2] += wv.w * xv.z; acc[3][3] += wv.w * xv.w;
            }
        }
        if (cc < 15)
            x_s[(cc + 1) & 1][sgg][sicc][sp4] = rn;
        __syncthreads();
    }

    const float mymask = myg ? m1v : m0;
    #pragma unroll
    for (int k = 0; k < 4; k++) {
        int gc = gp * 64 + ocq * 4 + k;
        float sc = g1[gc] * rsqrtf(v1[gc] + EPSV);
        float bi = b1[gc] - m1[gc] * sc;
        float4 v;
        if (mymask != 0.0f) {
            v.x = fmaxf(acc[k][0] * sc + bi, 0.0f);
            v.y = fmaxf(acc[k][1] * sc + bi, 0.0f);
            v.z = fmaxf(acc[k][2] * sc + bi, 0.0f);
            v.w = fmaxf(acc[k][3] * sc + bi, 0.0f);
        } else {
            v = make_float4(0.f, 0.f, 0.f, 0.f);
        }
        *(float4*)&g_y1[((b * MID + gc) * H + h0 + r) * W + w0 + cst] = v;
    }
}

// ---------------------------------------------------------------------------
// Kernel 2: 3x3 grouped conv (128->128, pad 1) + BN + ReLU + mask.
// CTA = (tile, group, batch), 128 thr, thread = 4px x 4oc.
// Single smem phase (halo + full weight slab, dynamic smem), one sync.
// Per ic: 18 scalar LDS + 9 LDS.128 + 144 FFMA.
// ---------------------------------------------------------------------------
#define K2_HALO   3200                     // 32 * 100 floats
#define K2_WSLAB  (32 * 9 * 36)            // [ic][tap][oc pad36]
#define K2_SMEM   ((K2_HALO + K2_WSLAB) * 4)

__global__ __launch_bounds__(128) void k2_conv2(
    const float* __restrict__ mask,
    const float* __restrict__ w2,
    const float* __restrict__ g2, const float* __restrict__ b2,
    const float* __restrict__ m2, const float* __restrict__ v2)
{
    const int bh = blockIdx.x / 7, bw = blockIdx.x % 7;
    const int g = blockIdx.y, b = blockIdx.z;
    const int h0 = bh * 8, w0 = bw * 8;
    const int t = threadIdx.x;
    const int pxq = t >> 3;                // [0,16)
    const int ocq = t & 7;                 // [0,8): 4-oc slice
    const int r = pxq >> 1, cst = (pxq & 1) * 4;

    const float m = mask[((b * GRP + g) * MH + bh) * MW + bw];

    if (m == 0.0f) {
        const float4 z = make_float4(0.f, 0.f, 0.f, 0.f);
        #pragma unroll
        for (int k = 0; k < 4; k++) {
            int gc = g * 32 + ocq * 4 + k;
            *(float4*)&g_y2[((b * MID + gc) * H + h0 + r) * W + w0 + cst] = z;
        }
        return;
    }

    extern __shared__ float sm[];
    float* in_s = sm;                      // [32][100]
    float* w_s  = sm + K2_HALO;            // [ic][tap][oc] = ic*324 + tap*36 + oc

    // halo (y1 already post-mask; zero-pad borders)
    for (int i = t; i < 32 * 100; i += 128) {
        int ic = i / 100, p = i % 100;
        int rr = h0 + p / 10 - 1, c2 = w0 + p % 10 - 1;
        float v = 0.0f;
        if (rr >= 0 && rr < H && c2 >= 0 && c2 < W)
            v = g_y1[((b * MID + g * 32 + ic) * H + rr) * W + c2];
        in_s[i / 100 * 100 + p] = v;
    }
    // weights: w2[(g*32+oc)*288 + ic*9 + kk] -> w_s[ic][kk][oc]
    const float* w2g = w2 + (g * 32) * 288;
    for (int i = t; i < 32 * 288; i += 128) {
        int oc = i / 288, rem = i % 288;
        int ic = rem / 9, kk = rem % 9;
        w_s[ic * 324 + kk * 36 + oc] = w2g[i];
    }
    __syncthreads();

    float acc[4][4];
    #pragma unroll
    for (int k = 0; k < 4; k++)
        #pragma unroll
        for (int q = 0; q < 4; q++) acc[k][q] = 0.0f;

    #pragma unroll 4
    for (int ic = 0; ic < 32; ic++) {
        float xr[3][6];
        #pragma unroll
        for (int kr = 0; kr < 3; kr++)
            #pragma unroll
            for (int j = 0; j < 6; j++)
                xr[kr][j] = in_s[ic * 100 + (r + kr) * 10 + cst + j];
        #pragma unroll
        for (int kr = 0; kr < 3; kr++) {
            #pragma unroll
            for (int kc = 0; kc < 3; kc++) {
                float4 wv = *(const float4*)&w_s[ic * 324 + (kr * 3 + kc) * 36 + ocq * 4];
                #pragma unroll
                for (int q = 0; q < 4; q++) {
                    float xv = xr[kr][q + kc];
                    acc[0][q] += wv.x * xv;
                    acc[1][q] += wv.y * xv;
                    acc[2][q] += wv.z * xv;
                    acc[3][q] += wv.w * xv;
                }
            }
        }
    }

    #pragma unroll
    for (int k = 0; k < 4; k++) {
        int gc = g * 32 + ocq * 4 + k;
        float sc = g2[gc] * rsqrtf(v2[gc] + EPSV);
        float bi = b2[gc] - m2[gc] * sc;
        float4 v;
        v.x = fmaxf(acc[k][0] * sc + bi, 0.0f);
        v.y = fmaxf(acc[k][1] * sc + bi, 0.0f);
        v.z = fmaxf(acc[k][2] * sc + bi, 0.0f);
        v.w = fmaxf(acc[k][3] * sc + bi, 0.0f);
        *(float4*)&g_y2[((b * MID + gc) * H + h0 + r) * W + w0 + cst] = v;
    }
}

// ---------------------------------------------------------------------------
// Kernel 3: 1x1 grouped conv (128->512) + BN + residual + ReLU.
// Thread: 4 px x 8 oc. Per ic: LDS.128(x) + 2x LDS.128(w) + 32 FFMA.
// mask==0 -> out = relu(bias3 + x).
// ---------------------------------------------------------------------------
__global__ __launch_bounds__(256) void k3_conv3(
    const float* __restrict__ x, const float* __restrict__ mask,
    const float* __restrict__ w3,
    const float* __restrict__ g3, const float* __restrict__ b3,
    const float* __restrict__ m3, const float* __restrict__ v3,
    float* __restrict__ out)
{
    const int bh = blockIdx.x / 7, bw = blockIdx.x % 7;
    const int g = blockIdx.y, b = blockIdx.z;
    const int h0 = bh * 8, w0 = bw * 8;
    const int t = threadIdx.x;
    const int pxq = t >> 4, ocp = t & 15;
    const int r = pxq >> 1, cst = (pxq & 1) * 4;

    const float m = mask[((b * GRP + g) * MH + bh) * MW + bw];

    if (m == 0.0f) {
        #pragma unroll
        for (int k = 0; k < 8; k++) {
            int gc = g * 128 + ocp * 8 + k;
            float sc = g3[gc] * rsqrtf(v3[gc] + EPSV);
            float bi = b3[gc] - m3[gc] * sc;
            long idx = ((long)(b * CIN + gc) * H + h0 + r) * W + w0 + cst;
            float4 xv = *(const float4*)&x[idx];
            float4 v;
            v.x = fmaxf(bi + xv.x, 0.0f);
            v.y = fmaxf(bi + xv.y, 0.0f);
            v.z = fmaxf(bi + xv.z, 0.0f);
            v.w = fmaxf(bi + xv.w, 0.0f);
            *(float4*)&out[idx] = v;
        }
        return;
    }

    __shared__ float  w_s[32][132];     // [ic][oc], padded
    __shared__ float4 y_s[32][16];      // [ic][pxq]

    const float* w3g = w3 + (g * 128) * 32;     // [oc=128][ic=32]
    #pragma unroll
    for (int i = t; i < 128 * 32; i += 256)
        w_s[i & 31][i >> 5] = w3g[i];
    #pragma unroll
    for (int j = 0; j < 2; j++) {
        int i = t + j * 256;
        int ic = i >> 4, p4 = i & 15;
        int rr = p4 >> 1, c2 = (p4 & 1) * 4;
        y_s[ic][p4] = *(const float4*)&g_y2[
            ((b * MID + g * 32 + ic) * H + h0 + rr) * W + w0 + c2];
    }
    __syncthreads();

    float acc[8][4];
    #pragma unroll
    for (int k = 0; k < 8; k++)
        #pragma unroll
        for (int q = 0; q < 4; q++) acc[k][q] = 0.0f;

    #pragma unroll 4
    for (int ic = 0; ic < 32; ic++) {
        float4 xv = y_s[ic][pxq];
        const float* wr = &w_s[ic][ocp * 8];
        float4 wa = *(const float4*)wr;
        float4 wb = *(const float4*)(wr + 4);
        float wk[8] = {wa.x, wa.y, wa.z, wa.w, wb.x, wb.y, wb.z, wb.w};
        #pragma unroll
        for (int k = 0; k < 8; k++) {
            acc[k][0] += wk[k] * xv.x;
            acc[k][1] += wk[k] * xv.y;
            acc[k][2] += wk[k] * xv.z;
            acc[k][3] += wk[k] * xv.w;
        }
    }

    #pragma unroll
    for (int k = 0; k < 8; k++) {
        int gc = g * 128 + ocp * 8 + k;
        float sc = g3[gc] * rsqrtf(v3[gc] + EPSV);
        float bi = b3[gc] - m3[gc] * sc;
        long idx = ((long)(b * CIN + gc) * H + h0 + r) * W + w0 + cst;
        float4 xv = *(const float4*)&x[idx];
        float4 v;
        v.x = fmaxf(acc[k][0] * sc + bi + xv.x, 0.0f);
        v.y = fmaxf(acc[k][1] * sc + bi + xv.y, 0.0f);
        v.z = fmaxf(acc[k][2] * sc + bi + xv.z, 0.0f);
        v.w = fmaxf(acc[k][3] * sc + bi + xv.w, 0.0f);
        *(float4*)&out[idx] = v;
    }
}

// ---------------------------------------------------------------------------
extern "C" void kernel_launch(void* const* d_in, const int* in_sizes, int n_in,
                              void* d_out, int out_size)
{
    const float* x    = (const float*)d_in[0];
    const float* mask = (const float*)d_in[1];
    const float* w1   = (const float*)d_in[2];
    const float* g1   = (const float*)d_in[3];
    const float* b1   = (const float*)d_in[4];
    const float* m1   = (const float*)d_in[5];
    const float* v1   = (const float*)d_in[6];
    const float* w2   = (const float*)d_in[7];
    const float* g2   = (const float*)d_in[8];
    const float* b2   = (const float*)d_in[9];
    const float* m2   = (const float*)d_in[10];
    const float* v2   = (const float*)d_in[11];
    const float* w3   = (const float*)d_in[12];
    const float* g3   = (const float*)d_in[13];
    const float* b3   = (const float*)d_in[14];
    const float* m3   = (const float*)d_in[15];
    const float* v3   = (const float*)d_in[16];
    float* out = (float*)d_out;

    cudaFuncSetAttribute(k2_conv2, cudaFuncAttributeMaxDynamicSharedMemorySize, K2_SMEM);

    dim3 grid1(49, 2, BATCH);
    k1_conv1<<<grid1, 256>>>(x, mask, w1, g1, b1, m1, v1);
    dim3 grid2(49, GRP, BATCH);
    k2_conv2<<<grid2, 128, K2_SMEM>>>(mask, w2, g2, b2, m2, v2);
    k3_conv3<<<grid2, 256>>>(x, mask, w3, g3, b3, m3, v3, out);
}